// round 15
// baseline (speedup 1.0000x reference)
#include <cuda_runtime.h>
#include <cstdint>

#define NB 4096
#define NS 64
#define ND 512
#define NDEPTH 4
#define LN_EPS 1e-5f

#define KTW 32     // packed words per ktile (= 64 k-values)
#define ASTR 36    // A smem row stride in words (32 data + 4 pad)
#define BSTRL 72   // B smem row stride in words (64 data + 8 pad)

#define GBLK 1024
#define GTHR 128
#define NGRP 128     // 128 groups x 8 CTAs; group owns 32 rows
#define GRP_BLKS 8
#define GROWS 32     // rows per group

#define A_ST_W (GROWS * ASTR)             // 1152 words per A stage
#define W_ST_W (KTW * BSTRL)              // 2304 words per B stage
#define SMEM_W (2 * A_ST_W + 2 * W_ST_W)  // 6912 words = 27648 B

#define F_RAW 0
#define F_EPI 1  // bias + relu + pack-to-bf16 (ff1 -> h)
#define F_RES 2  // x += acc + bias (Wc residual RMW)

// Activation scratch
static __device__ __align__(128) float g_x[NB * ND];           // residual (fp32)
static __device__ __align__(128) uint32_t g_yp[NB * ND / 2];   // LN out, bf16x2 packed
static __device__ __align__(128) uint32_t g_hp[NB * 2 * ND];   // ff1 out, bf16x2 packed
static __device__ __align__(128) float g_p0[NB * ND];          // ff2 split-K partial 0
static __device__ __align__(128) float g_p1[NB * ND];          // ff2 split-K partial 1
// Packed weights: word (kk, n) = (bf16 W[2kk][n], bf16 W[2kk+1][n])
static __device__ __align__(128) uint32_t g_wcp[NDEPTH * (ND / 2) * ND];
static __device__ __align__(128) uint32_t g_w1p[NDEPTH * (ND / 2) * 4 * ND];
static __device__ __align__(128) uint32_t g_w2p[NDEPTH * 2 * ND * ND];
static __device__ float g_bc[NDEPTH * ND];  // bv @ Wo + bo (fp32)

// Global barrier (used once) + per-group barriers (own cachelines)
static __device__ unsigned g_bar = 0;
static __device__ volatile unsigned g_epoch = 0;
static __device__ __align__(128) unsigned g_gcnt[NGRP * 32];
static __device__ __align__(128) volatile unsigned g_gep[NGRP * 32];

__device__ __forceinline__ void grid_bar() {
    __threadfence();
    __syncthreads();
    if (threadIdx.x == 0) {
        unsigned e = g_epoch;
        if (atomicAdd(&g_bar, 1u) == GBLK - 1) {
            g_bar = 0;
            __threadfence();
            g_epoch = e + 1;
        } else {
            while (g_epoch == e) __nanosleep(32);
            __threadfence();
        }
    }
    __syncthreads();
}

__device__ __forceinline__ void group_bar(int g) {
    __threadfence();
    __syncthreads();
    if (threadIdx.x == 0) {
        unsigned e = g_gep[g * 32];
        if (atomicAdd(&g_gcnt[g * 32], 1u) == GRP_BLKS - 1) {
            g_gcnt[g * 32] = 0;
            __threadfence();
            g_gep[g * 32] = e + 1;
        } else {
            while (g_gep[g * 32] == e) __nanosleep(20);
            __threadfence();
        }
    }
    __syncthreads();
}

__device__ __forceinline__ float warp_sum(float v) {
#pragma unroll
    for (int o = 16; o > 0; o >>= 1) v += __shfl_xor_sync(0xffffffffu, v, o);
    return v;
}

__device__ __forceinline__ uint32_t pkbf(float lo, float hi) {
    uint32_t r;
    asm("cvt.rn.bf16x2.f32 %0, %1, %2;" : "=r"(r) : "f"(hi), "f"(lo));
    return r;
}

__device__ __forceinline__ void cpasync16(void* smem, const void* gmem) {
    uint32_t sa = (uint32_t)__cvta_generic_to_shared(smem);
    asm volatile("cp.async.cg.shared.global [%0], [%1], 16;\n" ::"r"(sa), "l"(gmem));
}

// ---------------------------------------------------------------------------
// One-time prep: Wc = Wv @ Wo packed to bf16 pairs; bc; pack ff1/ff2.
// ---------------------------------------------------------------------------
__device__ void prep_phase(const float* __restrict__ qkv_w, const float* __restrict__ qkv_b,
                           const float* __restrict__ out_w, const float* __restrict__ out_b,
                           const float* __restrict__ ff1_w, const float* __restrict__ ff2_w) {
    const int gtid = blockIdx.x * GTHR + threadIdx.x;
    const int stride = GBLK * GTHR;
    for (int i = gtid; i < NDEPTH * (ND / 2) * ND; i += stride) {
        int n = i & (ND - 1), kk = (i >> 9) & (ND / 2 - 1), l = i >> 17;
        const float* wv0 = qkv_w + ((size_t)l * ND + 2 * kk) * (3 * ND) + 2 * ND;
        const float* wv1 = wv0 + 3 * ND;
        const float* wo = out_w + (size_t)l * ND * ND + n;
        float s0 = 0.f, s1 = 0.f;
#pragma unroll 4
        for (int j = 0; j < ND; j++) {
            float w = wo[(size_t)j * ND];
            s0 += wv0[j] * w;
            s1 += wv1[j] * w;
        }
        g_wcp[i] = pkbf(s0, s1);
    }
    for (int i = gtid; i < NDEPTH * ND; i += stride) {
        int n = i & (ND - 1), l = i >> 9;
        const float* bv = qkv_b + l * 3 * ND + 2 * ND;
        const float* wo = out_w + (size_t)l * ND * ND + n;
        float s = out_b[l * ND + n];
#pragma unroll 4
        for (int j = 0; j < ND; j++) s += bv[j] * wo[(size_t)j * ND];
        g_bc[i] = s;
    }
    for (int i = gtid; i < NDEPTH * (ND / 2) * 4 * ND; i += stride) {
        int n = i & (4 * ND - 1), kk = (i >> 11) & (ND / 2 - 1), l = i >> 19;
        size_t base = ((size_t)l * ND + 2 * kk) * (4 * ND) + n;
        g_w1p[i] = pkbf(ff1_w[base], ff1_w[base + 4 * ND]);
    }
    for (int i = gtid; i < NDEPTH * 2 * ND * ND; i += stride) {
        int n = i & (ND - 1), kk = (i >> 9) & (2 * ND - 1), l = i >> 19;
        size_t base = ((size_t)l * 4 * ND + 2 * kk) * ND + n;
        g_w2p[i] = pkbf(ff2_w[base], ff2_w[base + ND]);
    }
}

// ---------------------------------------------------------------------------
// emb0: one row per warp (4096 warps total)
// ---------------------------------------------------------------------------
__device__ void emb0_phase(const int* __restrict__ a_seq, const int* __restrict__ b_seq,
                           const float* __restrict__ emb, const float* __restrict__ start) {
    int row = blockIdx.x * 4 + (threadIdx.x >> 5);
    int lane = threadIdx.x & 31;
    int a = a_seq[row * NS];
    int b = b_seq[row * NS];
    const float4* ea = (const float4*)(emb + (size_t)a * ND);
    const float4* eb = (const float4*)(emb + (size_t)b * ND);
    const float4* ss = (const float4*)start;
    float4* xr = (float4*)(g_x + (size_t)row * ND);
#pragma unroll
    for (int j = 0; j < 4; j++) {
        int c = lane + 32 * j;
        float4 va = ea[c], vb = eb[c], vs = ss[c];
        float4 o;
        o.x = va.x + vb.x + vs.x;
        o.y = va.y + vb.y + vs.y;
        o.z = va.z + vb.z + vs.z;
        o.w = va.w + vb.w + vs.w;
        xr[c] = o;
    }
}

// ---------------------------------------------------------------------------
// Group-scoped LN: 32 warps in group handle 32 rows (1 row/warp).
// ---------------------------------------------------------------------------
template <bool FUSE>
__device__ void ln_phase(int group, int rank, float* __restrict__ x,
                         uint32_t* __restrict__ yp, const float* __restrict__ p0,
                         const float* __restrict__ p1, const float* __restrict__ addb,
                         const float* __restrict__ g, const float* __restrict__ b) {
    int row = group * GROWS + rank * 4 + (threadIdx.x >> 5);
    int lane = threadIdx.x & 31;
    float4* xr = (float4*)(x + (size_t)row * ND);
    float4 v[4];
    float s = 0.f;
#pragma unroll
    for (int j = 0; j < 4; j++) {
        int c = lane + 32 * j;
        v[j] = xr[c];
        if (FUSE) {
            float4 a0 = ((const float4*)(p0 + (size_t)row * ND))[c];
            float4 a1 = ((const float4*)(p1 + (size_t)row * ND))[c];
            float4 ab = ((const float4*)addb)[c];
            v[j].x += a0.x + a1.x + ab.x;
            v[j].y += a0.y + a1.y + ab.y;
            v[j].z += a0.z + a1.z + ab.z;
            v[j].w += a0.w + a1.w + ab.w;
            xr[c] = v[j];
        }
        s += v[j].x + v[j].y + v[j].z + v[j].w;
    }
    s = warp_sum(s);
    float mean = s * (1.0f / ND);
    float q = 0.f;
#pragma unroll
    for (int j = 0; j < 4; j++) {
        float cx = v[j].x - mean, cy = v[j].y - mean;
        float cz = v[j].z - mean, cw = v[j].w - mean;
        q += cx * cx + cy * cy + cz * cz + cw * cw;
    }
    q = warp_sum(q);
    float r = rsqrtf(q * (1.0f / ND) + LN_EPS);
    uint2* yr = (uint2*)(yp + (size_t)row * (ND / 2));
#pragma unroll
    for (int j = 0; j < 4; j++) {
        int c = lane + 32 * j;
        float4 gg = ((const float4*)g)[c];
        float4 bb = ((const float4*)b)[c];
        uint2 o;
        o.x = pkbf((v[j].x - mean) * r * gg.x + bb.x, (v[j].y - mean) * r * gg.y + bb.y);
        o.y = pkbf((v[j].z - mean) * r * gg.z + bb.z, (v[j].w - mean) * r * gg.w + bb.w);
        yr[c] = o;
    }
}

// ---------------------------------------------------------------------------
// Group-scoped head with fused ff2 reduce (1 row/warp).
// ---------------------------------------------------------------------------
__device__ void heademb_phase(int group, int rank, const float* __restrict__ p0,
                              const float* __restrict__ p1, const float* __restrict__ addb,
                              const float* __restrict__ hw, const float* __restrict__ hb,
                              float* __restrict__ out, const int* __restrict__ a_seq,
                              const int* __restrict__ b_seq, const float* __restrict__ emb,
                              int t) {
    int row = group * GROWS + rank * 4 + (threadIdx.x >> 5);
    int lane = threadIdx.x & 31;
    float4* xr = (float4*)(g_x + (size_t)row * ND);
    float4 v[4];
    float s0 = 0.f, s1 = 0.f;
#pragma unroll
    for (int j = 0; j < 4; j++) {
        int c = lane + 32 * j;
        v[j] = xr[c];
        float4 a0 = ((const float4*)(p0 + (size_t)row * ND))[c];
        float4 a1 = ((const float4*)(p1 + (size_t)row * ND))[c];
        float4 ab = ((const float4*)addb)[c];
        v[j].x += a0.x + a1.x + ab.x;
        v[j].y += a0.y + a1.y + ab.y;
        v[j].z += a0.z + a1.z + ab.z;
        v[j].w += a0.w + a1.w + ab.w;
#pragma unroll
        for (int u = 0; u < 4; u++) {
            float xv = (&v[j].x)[u];
            float2 wv = ((const float2*)hw)[c * 4 + u];
            s0 += xv * wv.x;
            s1 += xv * wv.y;
        }
    }
    s0 = warp_sum(s0);
    s1 = warp_sum(s1);
    if (lane == 0) {
        out[(size_t)row * NS * 2 + t * 2 + 0] = s0 + hb[0];
        out[(size_t)row * NS * 2 + t * 2 + 1] = s1 + hb[1];
    }
    if (t + 1 < NS) {
        int a = a_seq[row * NS + t + 1];
        int b = b_seq[row * NS + t + 1];
        const float4* ea = (const float4*)(emb + (size_t)a * ND);
        const float4* eb = (const float4*)(emb + (size_t)b * ND);
#pragma unroll
        for (int j = 0; j < 4; j++) {
            int c = lane + 32 * j;
            v[j].x += ea[c].x + eb[c].x;
            v[j].y += ea[c].y + eb[c].y;
            v[j].z += ea[c].z + eb[c].z;
            v[j].w += ea[c].w + eb[c].w;
            xr[c] = v[j];
        }
    } else {
#pragma unroll
        for (int j = 0; j < 4; j++) xr[lane + 32 * j] = v[j];
    }
}

// ---------------------------------------------------------------------------
// BF16 GEMM: 4-warp CTA, block tile 32x64 (warps tile N: 16 cols each),
// mma.m16n8k16 (fp32 acc), ktile = 64 k, 2-stage cp.async, A via ldmatrix.x4.
// ---------------------------------------------------------------------------
template <int FLAGS>
__device__ void gemm_phase(int group, int rank, const uint32_t* __restrict__ Aw, int Kw,
                           const uint32_t* __restrict__ Wp, int ldw,
                           const float* __restrict__ bias, float* __restrict__ Cx,
                           float* __restrict__ C0, float* __restrict__ C1,
                           uint32_t* __restrict__ C0p, int N, int KT, int nsplit,
                           uint32_t* sm) {
    uint32_t* sA = sm;
    uint32_t* sW = sm + 2 * A_ST_W;

    const int tid = threadIdx.x;
    const int warp = tid >> 5, lane = tid & 31;
    const int gid = lane >> 2, tig = lane & 3;

    const int bcol = warp * 16 + gid;

    // ldmatrix lane address (bytes within A stage), constant per job:
    const uint32_t a_lane_off =
        ((uint32_t)(((lane & 7) + ((lane >> 3) & 1) * 8) * ASTR + (lane >> 4) * 4)) << 2;
    const uint32_t sA_sh = (uint32_t)__cvta_generic_to_shared(sA);

    const int nT = N >> 6;  // BN = 64
    const int njobs = nT * nsplit;

    for (int job = rank; job < njobs; job += GRP_BLKS) {
        const int split = job / nT;
        const int bn = job % nT;
        const uint32_t* Ag = Aw + (size_t)(group * GROWS) * Kw + split * KT * KTW;
        const uint32_t* Wg = Wp + (size_t)(split * KT * KTW) * ldw + bn * 64;

        float acc[2][2][4];
#pragma unroll
        for (int i = 0; i < 2; i++)
#pragma unroll
            for (int j = 0; j < 2; j++)
#pragma unroll
                for (int k = 0; k < 4; k++) acc[i][j][k] = 0.f;

        auto load_tiles = [&](int kt, int st) {
            uint32_t* dA = sA + st * A_ST_W;
            const uint32_t* srcA = Ag + kt * KTW;
#pragma unroll
            for (int i = 0; i < 2; i++) {
                int c = tid + i * 128;
                int row = c >> 3, ch = c & 7;  // 32 rows x 8 chunks
                cpasync16(dA + row * ASTR + ch * 4, srcA + (size_t)row * Kw + ch * 4);
            }
            uint32_t* dW = sW + st * W_ST_W;
            const uint32_t* srcW = Wg + (size_t)kt * KTW * ldw;
#pragma unroll
            for (int i = 0; i < 4; i++) {
                int c = tid + i * 128;
                int row = c >> 4, ch = c & 15;  // 32 rows x 16 chunks
                cpasync16(dW + row * BSTRL + ch * 4, srcW + (size_t)row * ldw + ch * 4);
            }
            asm volatile("cp.async.commit_group;\n");
        };

        load_tiles(0, 0);
        if (KT > 1) load_tiles(1, 1);

        for (int kt = 0; kt < KT; ++kt) {
            if (kt == KT - 1) {
                asm volatile("cp.async.wait_group 0;\n");
            } else {
                asm volatile("cp.async.wait_group 1;\n");
            }
            __syncthreads();
            const uint32_t aBase = sA_sh + (uint32_t)((kt & 1) * A_ST_W * 4) + a_lane_off;
            const uint32_t* w_ = sW + (kt & 1) * W_ST_W;
#pragma unroll
            for (int ks = 0; ks < 4; ++ks) {
                uint32_t af[2][4];
#pragma unroll
                for (int mi = 0; mi < 2; ++mi) {
                    uint32_t addr = aBase + (uint32_t)((mi * 16 * ASTR + ks * 8) * 4);
                    asm volatile(
                        "ldmatrix.sync.aligned.m8n8.x4.shared.b16 {%0,%1,%2,%3}, [%4];"
                        : "=r"(af[mi][0]), "=r"(af[mi][1]), "=r"(af[mi][2]), "=r"(af[mi][3])
                        : "r"(addr));
                }
                const int brow = (ks * 8 + tig) * BSTRL + bcol;
#pragma unroll
                for (int ni = 0; ni < 2; ++ni) {
                    uint32_t b0 = w_[brow + ni * 8];
                    uint32_t b1 = w_[brow + 4 * BSTRL + ni * 8];
#pragma unroll
                    for (int mi = 0; mi < 2; ++mi) {
                        asm volatile(
                            "mma.sync.aligned.m16n8k16.row.col.f32.bf16.bf16.f32 "
                            "{%0,%1,%2,%3},{%4,%5,%6,%7},{%8,%9},{%0,%1,%2,%3};\n"
                            : "+f"(acc[mi][ni][0]), "+f"(acc[mi][ni][1]),
                              "+f"(acc[mi][ni][2]), "+f"(acc[mi][ni][3])
                            : "r"(af[mi][0]), "r"(af[mi][1]), "r"(af[mi][2]), "r"(af[mi][3]),
                              "r"(b0), "r"(b1));
                    }
                }
            }
            __syncthreads();
            if (kt + 2 < KT) load_tiles(kt + 2, kt & 1);
        }

        float* C = (FLAGS == F_RAW) ? (split ? C1 : C0) : nullptr;
#pragma unroll
        for (int mi = 0; mi < 2; mi++) {
            int row0 = group * GROWS + mi * 16 + gid;
#pragma unroll
            for (int ni = 0; ni < 2; ni++) {
                int col = bn * 64 + warp * 16 + ni * 8 + tig * 2;
                if (FLAGS == F_RES) {
                    float2 bv = *(const float2*)(bias + col);
                    float2* px0 = (float2*)(Cx + (size_t)row0 * N + col);
                    float2* px1 = (float2*)(Cx + (size_t)(row0 + 8) * N + col);
                    float2 x0 = *px0, x1 = *px1;
                    x0.x += acc[mi][ni][0] + bv.x;
                    x0.y += acc[mi][ni][1] + bv.y;
                    x1.x += acc[mi][ni][2] + bv.x;
                    x1.y += acc[mi][ni][3] + bv.y;
                    *px0 = x0;
                    *px1 = x1;
                } else if (FLAGS == F_EPI) {
                    float2 bv = *(const float2*)(bias + col);
                    float x0 = fmaxf(acc[mi][ni][0] + bv.x, 0.f);
                    float y0 = fmaxf(acc[mi][ni][1] + bv.y, 0.f);
                    float x1 = fmaxf(acc[mi][ni][2] + bv.x, 0.f);
                    float y1 = fmaxf(acc[mi][ni][3] + bv.y, 0.f);
                    C0p[(size_t)row0 * (N / 2) + (col >> 1)] = pkbf(x0, y0);
                    C0p[(size_t)(row0 + 8) * (N / 2) + (col >> 1)] = pkbf(x1, y1);
                } else {
                    float2 v0, v1;
                    v0.x = acc[mi][ni][0];
                    v0.y = acc[mi][ni][1];
                    v1.x = acc[mi][ni][2];
                    v1.y = acc[mi][ni][3];
                    *(float2*)(C + (size_t)row0 * N + col) = v0;
                    *(float2*)(C + (size_t)(row0 + 8) * N + col) = v1;
                }
            }
        }
    }
}

// ---------------------------------------------------------------------------
// Persistent kernel: 1024 CTAs (7/SM), 8-CTA groups own 32 rows.
// ---------------------------------------------------------------------------
__global__ __launch_bounds__(GTHR, 7) void persistent_kernel(
    const int* __restrict__ a_seq, const int* __restrict__ b_seq,
    const float* __restrict__ bit_emb, const float* __restrict__ start_state,
    const float* __restrict__ ln1_g, const float* __restrict__ ln1_b,
    const float* __restrict__ qkv_w, const float* __restrict__ qkv_b,
    const float* __restrict__ out_w, const float* __restrict__ out_b,
    const float* __restrict__ ln2_g, const float* __restrict__ ln2_b,
    const float* __restrict__ ff1_w, const float* __restrict__ ff1_b,
    const float* __restrict__ ff2_w, const float* __restrict__ ff2_b,
    const float* __restrict__ head_w, const float* __restrict__ head_b, float* __restrict__ out) {
    extern __shared__ uint32_t sm[];

    const int group = blockIdx.x >> 3;
    const int rank = blockIdx.x & 7;

    prep_phase(qkv_w, qkv_b, out_w, out_b, ff1_w, ff2_w);
    emb0_phase(a_seq, b_seq, bit_emb, start_state);
    grid_bar();

    for (int t = 0; t < NS; ++t) {
        for (int l = 0; l < NDEPTH; ++l) {
            if (l == 0)
                ln_phase<false>(group, rank, g_x, g_yp, nullptr, nullptr, nullptr,
                                ln1_g + l * ND, ln1_b + l * ND);
            else
                ln_phase<true>(group, rank, g_x, g_yp, g_p0, g_p1,
                               ff2_b + (size_t)(l - 1) * ND, ln1_g + l * ND, ln1_b + l * ND);
            group_bar(group);
            // Wc GEMM: x += y @ Wc + bc  (BN=64, 8 jobs, KT=8, residual RMW)
            gemm_phase<F_RES>(group, rank, g_yp, ND / 2, g_wcp + (size_t)l * (ND / 2) * ND, ND,
                              g_bc + l * ND, g_x, nullptr, nullptr, nullptr, ND, 8, 1, sm);
            group_bar(group);
            // LN2 plain
            ln_phase<false>(group, rank, g_x, g_yp, nullptr, nullptr, nullptr, ln2_g + l * ND,
                            ln2_b + l * ND);
            group_bar(group);
            // h = pack(relu(y @ W1 + b1))  (BN=64, 32 jobs, KT=8)
            gemm_phase<F_EPI>(group, rank, g_yp, ND / 2, g_w1p + (size_t)l * (ND / 2) * 4 * ND,
                              4 * ND, ff1_b + (size_t)l * 4 * ND, nullptr, nullptr, nullptr,
                              g_hp, 4 * ND, 8, 1, sm);
            group_bar(group);
            // ff2 (split-K 2, KT=16): p0/p1 = h @ W2  (BN=64, 16 jobs)
            gemm_phase<F_RAW>(group, rank, g_hp, 2 * ND, g_w2p + (size_t)l * 2 * ND * ND, ND,
                              nullptr, nullptr, g_p0, g_p1, nullptr, ND, 16, 2, sm);
            group_bar(group);
        }
        heademb_phase(group, rank, g_p0, g_p1, ff2_b + (size_t)(NDEPTH - 1) * ND, head_w,
                      head_b, out, a_seq, b_seq, bit_emb, t);
        group_bar(group);
    }
}

// ---------------------------------------------------------------------------
extern "C" void kernel_launch(void* const* d_in, const int* in_sizes, int n_in,
                              void* d_out, int out_size) {
    const int* a_seq = (const int*)d_in[0];
    const int* b_seq = (const int*)d_in[1];
    const float* bit_emb = (const float*)d_in[2];
    const float* start_state = (const float*)d_in[3];
    const float* ln1_g = (const float*)d_in[4];
    const float* ln1_b = (const float*)d_in[5];
    const float* qkv_w = (const float*)d_in[6];
    const float* qkv_b = (const float*)d_in[7];
    const float* out_w = (const float*)d_in[8];
    const float* out_b = (const float*)d_in[9];
    const float* ln2_g = (const float*)d_in[10];
    const float* ln2_b = (const float*)d_in[11];
    const float* ff1_w = (const float*)d_in[12];
    const float* ff1_b = (const float*)d_in[13];
    const float* ff2_w = (const float*)d_in[14];
    const float* ff2_b = (const float*)d_in[15];
    const float* head_w = (const float*)d_in[16];
    const float* head_b = (const float*)d_in[17];
    float* out = (float*)d_out;

    const int smem = SMEM_W * (int)sizeof(uint32_t);
    static int configured = 0;
    if (!configured) {
        cudaFuncSetAttribute(persistent_kernel, cudaFuncAttributeMaxDynamicSharedMemorySize, smem);
        configured = 1;
    }

    persistent_kernel<<<GBLK, GTHR, smem>>>(a_seq, b_seq, bit_emb, start_state, ln1_g, ln1_b,
                                            qkv_w, qkv_b, out_w, out_b, ln2_g, ln2_b, ff1_w,
                                            ff1_b, ff2_w, ff2_b, head_w, head_b, out);
}

// round 16
// speedup vs baseline: 1.1011x; 1.1011x over previous
#include <cuda_runtime.h>
#include <cstdint>

#define NB 4096
#define NS 64
#define ND 512
#define NDEPTH 4
#define LN_EPS 1e-5f

#define KTW 16    // packed words per ktile (= 32 k-values)
#define ASTR 20   // A smem row stride in words (16 data + 4 pad)
#define BSTR 136  // B smem row stride in words (128 data + 8 pad)

#define GBLK 1024
#define GTHR 128
#define NGRP 128     // 128 groups x 8 CTAs; group owns 32 rows
#define GRP_BLKS 8
#define GROWS 32     // rows per group

#define A_ST_W (GROWS * ASTR)             // 640 words per A stage
#define W_ST_W (KTW * BSTR)               // 2176 words per B stage
#define SMEM_W (2 * A_ST_W + 2 * W_ST_W)  // 5632 words = 22528 B

#define F_RAW 0
#define F_EPI 1  // bias + relu + pack-to-bf16 (ff1 -> h)

// Activation scratch
static __device__ __align__(128) float g_x[NB * ND];           // residual (fp32)
static __device__ __align__(128) uint32_t g_yp[NB * ND / 2];   // LN out, bf16x2 packed
static __device__ __align__(128) uint32_t g_hp[NB * 2 * ND];   // ff1 out, bf16x2 packed
static __device__ __align__(128) float g_p0[NB * ND];          // split-K partial 0
static __device__ __align__(128) float g_p1[NB * ND];          // split-K partial 1
// Packed weights: word (kk, n) = (bf16 W[2kk][n], bf16 W[2kk+1][n])
static __device__ __align__(128) uint32_t g_wcp[NDEPTH * (ND / 2) * ND];
static __device__ __align__(128) uint32_t g_w1p[NDEPTH * (ND / 2) * 4 * ND];
static __device__ __align__(128) uint32_t g_w2p[NDEPTH * 2 * ND * ND];
static __device__ float g_bc[NDEPTH * ND];  // bv @ Wo + bo (fp32)

// Global barrier (used once) + per-group barriers (own cachelines)
static __device__ unsigned g_bar = 0;
static __device__ volatile unsigned g_epoch = 0;
static __device__ __align__(128) unsigned g_gcnt[NGRP * 32];
static __device__ __align__(128) volatile unsigned g_gep[NGRP * 32];

__device__ __forceinline__ void grid_bar() {
    __threadfence();
    __syncthreads();
    if (threadIdx.x == 0) {
        unsigned e = g_epoch;
        if (atomicAdd(&g_bar, 1u) == GBLK - 1) {
            g_bar = 0;
            __threadfence();
            g_epoch = e + 1;
        } else {
            while (g_epoch == e) __nanosleep(32);
            __threadfence();
        }
    }
    __syncthreads();
}

__device__ __forceinline__ void group_bar(int g) {
    __threadfence();
    __syncthreads();
    if (threadIdx.x == 0) {
        unsigned e = g_gep[g * 32];
        if (atomicAdd(&g_gcnt[g * 32], 1u) == GRP_BLKS - 1) {
            g_gcnt[g * 32] = 0;
            __threadfence();
            g_gep[g * 32] = e + 1;
        } else {
            while (g_gep[g * 32] == e) __nanosleep(20);
            __threadfence();
        }
    }
    __syncthreads();
}

__device__ __forceinline__ float warp_sum(float v) {
#pragma unroll
    for (int o = 16; o > 0; o >>= 1) v += __shfl_xor_sync(0xffffffffu, v, o);
    return v;
}

__device__ __forceinline__ uint32_t pkbf(float lo, float hi) {
    uint32_t r;
    asm("cvt.rn.bf16x2.f32 %0, %1, %2;" : "=r"(r) : "f"(hi), "f"(lo));
    return r;
}

__device__ __forceinline__ void cpasync16(void* smem, const void* gmem) {
    uint32_t sa = (uint32_t)__cvta_generic_to_shared(smem);
    asm volatile("cp.async.cg.shared.global [%0], [%1], 16;\n" ::"r"(sa), "l"(gmem));
}

// ---------------------------------------------------------------------------
// One-time prep: Wc = Wv @ Wo packed to bf16 pairs; bc; pack ff1/ff2.
// ---------------------------------------------------------------------------
__device__ void prep_phase(const float* __restrict__ qkv_w, const float* __restrict__ qkv_b,
                           const float* __restrict__ out_w, const float* __restrict__ out_b,
                           const float* __restrict__ ff1_w, const float* __restrict__ ff2_w) {
    const int gtid = blockIdx.x * GTHR + threadIdx.x;
    const int stride = GBLK * GTHR;
    for (int i = gtid; i < NDEPTH * (ND / 2) * ND; i += stride) {
        int n = i & (ND - 1), kk = (i >> 9) & (ND / 2 - 1), l = i >> 17;
        const float* wv0 = qkv_w + ((size_t)l * ND + 2 * kk) * (3 * ND) + 2 * ND;
        const float* wv1 = wv0 + 3 * ND;
        const float* wo = out_w + (size_t)l * ND * ND + n;
        float s0 = 0.f, s1 = 0.f;
#pragma unroll 4
        for (int j = 0; j < ND; j++) {
            float w = wo[(size_t)j * ND];
            s0 += wv0[j] * w;
            s1 += wv1[j] * w;
        }
        g_wcp[i] = pkbf(s0, s1);
    }
    for (int i = gtid; i < NDEPTH * ND; i += stride) {
        int n = i & (ND - 1), l = i >> 9;
        const float* bv = qkv_b + l * 3 * ND + 2 * ND;
        const float* wo = out_w + (size_t)l * ND * ND + n;
        float s = out_b[l * ND + n];
#pragma unroll 4
        for (int j = 0; j < ND; j++) s += bv[j] * wo[(size_t)j * ND];
        g_bc[i] = s;
    }
    for (int i = gtid; i < NDEPTH * (ND / 2) * 4 * ND; i += stride) {
        int n = i & (4 * ND - 1), kk = (i >> 11) & (ND / 2 - 1), l = i >> 19;
        size_t base = ((size_t)l * ND + 2 * kk) * (4 * ND) + n;
        g_w1p[i] = pkbf(ff1_w[base], ff1_w[base + 4 * ND]);
    }
    for (int i = gtid; i < NDEPTH * 2 * ND * ND; i += stride) {
        int n = i & (ND - 1), kk = (i >> 9) & (2 * ND - 1), l = i >> 19;
        size_t base = ((size_t)l * 4 * ND + 2 * kk) * ND + n;
        g_w2p[i] = pkbf(ff2_w[base], ff2_w[base + ND]);
    }
}

// ---------------------------------------------------------------------------
// emb0: one row per warp (4096 warps total)
// ---------------------------------------------------------------------------
__device__ void emb0_phase(const int* __restrict__ a_seq, const int* __restrict__ b_seq,
                           const float* __restrict__ emb, const float* __restrict__ start) {
    int row = blockIdx.x * 4 + (threadIdx.x >> 5);
    int lane = threadIdx.x & 31;
    int a = a_seq[row * NS];
    int b = b_seq[row * NS];
    const float4* ea = (const float4*)(emb + (size_t)a * ND);
    const float4* eb = (const float4*)(emb + (size_t)b * ND);
    const float4* ss = (const float4*)start;
    float4* xr = (float4*)(g_x + (size_t)row * ND);
#pragma unroll
    for (int j = 0; j < 4; j++) {
        int c = lane + 32 * j;
        float4 va = ea[c], vb = eb[c], vs = ss[c];
        float4 o;
        o.x = va.x + vb.x + vs.x;
        o.y = va.y + vb.y + vs.y;
        o.z = va.z + vb.z + vs.z;
        o.w = va.w + vb.w + vs.w;
        xr[c] = o;
    }
}

// ---------------------------------------------------------------------------
// Group-scoped LN: 32 warps in group handle 32 rows (1 row/warp).
// Optional fused split-K reduce (x += p0+p1+addb); writes y packed bf16x2.
// ---------------------------------------------------------------------------
template <bool FUSE>
__device__ void ln_phase(int group, int rank, float* __restrict__ x,
                         uint32_t* __restrict__ yp, const float* __restrict__ p0,
                         const float* __restrict__ p1, const float* __restrict__ addb,
                         const float* __restrict__ g, const float* __restrict__ b) {
    int row = group * GROWS + rank * 4 + (threadIdx.x >> 5);
    int lane = threadIdx.x & 31;
    float4* xr = (float4*)(x + (size_t)row * ND);
    float4 v[4];
    float s = 0.f;
#pragma unroll
    for (int j = 0; j < 4; j++) {
        int c = lane + 32 * j;
        v[j] = xr[c];
        if (FUSE) {
            float4 a0 = ((const float4*)(p0 + (size_t)row * ND))[c];
            float4 a1 = ((const float4*)(p1 + (size_t)row * ND))[c];
            float4 ab = ((const float4*)addb)[c];
            v[j].x += a0.x + a1.x + ab.x;
            v[j].y += a0.y + a1.y + ab.y;
            v[j].z += a0.z + a1.z + ab.z;
            v[j].w += a0.w + a1.w + ab.w;
            xr[c] = v[j];
        }
        s += v[j].x + v[j].y + v[j].z + v[j].w;
    }
    s = warp_sum(s);
    float mean = s * (1.0f / ND);
    float q = 0.f;
#pragma unroll
    for (int j = 0; j < 4; j++) {
        float cx = v[j].x - mean, cy = v[j].y - mean;
        float cz = v[j].z - mean, cw = v[j].w - mean;
        q += cx * cx + cy * cy + cz * cz + cw * cw;
    }
    q = warp_sum(q);
    float r = rsqrtf(q * (1.0f / ND) + LN_EPS);
    uint2* yr = (uint2*)(yp + (size_t)row * (ND / 2));
#pragma unroll
    for (int j = 0; j < 4; j++) {
        int c = lane + 32 * j;
        float4 gg = ((const float4*)g)[c];
        float4 bb = ((const float4*)b)[c];
        uint2 o;
        o.x = pkbf((v[j].x - mean) * r * gg.x + bb.x, (v[j].y - mean) * r * gg.y + bb.y);
        o.y = pkbf((v[j].z - mean) * r * gg.z + bb.z, (v[j].w - mean) * r * gg.w + bb.w);
        yr[c] = o;
    }
}

// ---------------------------------------------------------------------------
// Group-scoped head with fused ff2 reduce (1 row/warp).
// ---------------------------------------------------------------------------
__device__ void heademb_phase(int group, int rank, const float* __restrict__ p0,
                              const float* __restrict__ p1, const float* __restrict__ addb,
                              const float* __restrict__ hw, const float* __restrict__ hb,
                              float* __restrict__ out, const int* __restrict__ a_seq,
                              const int* __restrict__ b_seq, const float* __restrict__ emb,
                              int t) {
    int row = group * GROWS + rank * 4 + (threadIdx.x >> 5);
    int lane = threadIdx.x & 31;
    float4* xr = (float4*)(g_x + (size_t)row * ND);
    float4 v[4];
    float s0 = 0.f, s1 = 0.f;
#pragma unroll
    for (int j = 0; j < 4; j++) {
        int c = lane + 32 * j;
        v[j] = xr[c];
        float4 a0 = ((const float4*)(p0 + (size_t)row * ND))[c];
        float4 a1 = ((const float4*)(p1 + (size_t)row * ND))[c];
        float4 ab = ((const float4*)addb)[c];
        v[j].x += a0.x + a1.x + ab.x;
        v[j].y += a0.y + a1.y + ab.y;
        v[j].z += a0.z + a1.z + ab.z;
        v[j].w += a0.w + a1.w + ab.w;
#pragma unroll
        for (int u = 0; u < 4; u++) {
            float xv = (&v[j].x)[u];
            float2 wv = ((const float2*)hw)[c * 4 + u];
            s0 += xv * wv.x;
            s1 += xv * wv.y;
        }
    }
    s0 = warp_sum(s0);
    s1 = warp_sum(s1);
    if (lane == 0) {
        out[(size_t)row * NS * 2 + t * 2 + 0] = s0 + hb[0];
        out[(size_t)row * NS * 2 + t * 2 + 1] = s1 + hb[1];
    }
    if (t + 1 < NS) {
        int a = a_seq[row * NS + t + 1];
        int b = b_seq[row * NS + t + 1];
        const float4* ea = (const float4*)(emb + (size_t)a * ND);
        const float4* eb = (const float4*)(emb + (size_t)b * ND);
#pragma unroll
        for (int j = 0; j < 4; j++) {
            int c = lane + 32 * j;
            v[j].x += ea[c].x + eb[c].x;
            v[j].y += ea[c].y + eb[c].y;
            v[j].z += ea[c].z + eb[c].z;
            v[j].w += ea[c].w + eb[c].w;
            xr[c] = v[j];
        }
    } else {
#pragma unroll
        for (int j = 0; j < 4; j++) xr[lane + 32 * j] = v[j];
    }
}

// ---------------------------------------------------------------------------
// BF16 GEMM: 4-warp CTA, block tile 32x128 (4 warps in N, warp tile 32x32),
// mma.m16n8k16 (fp32 acc), ktile = 32 k (16 words), 2-stage cp.async,
// A via ldmatrix.x4. acc = 32 regs/thread (fits 7 CTAs/SM).
// ---------------------------------------------------------------------------
template <int FLAGS>
__device__ void gemm_phase(int group, int rank, const uint32_t* __restrict__ Aw, int Kw,
                           const uint32_t* __restrict__ Wp, int ldw,
                           const float* __restrict__ bias, float* __restrict__ C0,
                           float* __restrict__ C1, uint32_t* __restrict__ C0p, int N, int KT,
                           int nsplit, uint32_t* sm) {
    uint32_t* sA = sm;
    uint32_t* sW = sm + 2 * A_ST_W;

    const int tid = threadIdx.x;
    const int warp = tid >> 5, lane = tid & 31;
    const int gid = lane >> 2, tig = lane & 3;

    const int bcol = warp * 32 + gid;

    // ldmatrix lane address (bytes within A stage), constant per job
    const uint32_t a_lane_off =
        ((uint32_t)(((lane & 7) + ((lane >> 3) & 1) * 8) * ASTR + (lane >> 4) * 4)) << 2;
    const uint32_t sA_sh = (uint32_t)__cvta_generic_to_shared(sA);

    const int nT = N >> 7;  // BN = 128
    const int njobs = nT * nsplit;

    for (int job = rank; job < njobs; job += GRP_BLKS) {
        const int split = job / nT;
        const int bn = job % nT;
        const uint32_t* Ag = Aw + (size_t)(group * GROWS) * Kw + split * KT * KTW;
        const uint32_t* Wg = Wp + (size_t)(split * KT * KTW) * ldw + bn * 128;

        float acc[2][4][4];
#pragma unroll
        for (int i = 0; i < 2; i++)
#pragma unroll
            for (int j = 0; j < 4; j++)
#pragma unroll
                for (int k = 0; k < 4; k++) acc[i][j][k] = 0.f;

        auto load_tiles = [&](int kt, int st) {
            uint32_t* dA = sA + st * A_ST_W;
            const uint32_t* srcA = Ag + kt * KTW;
            {
                int row = tid >> 2, ch = tid & 3;  // 32 rows x 4 chunks
                cpasync16(dA + row * ASTR + ch * 4, srcA + (size_t)row * Kw + ch * 4);
            }
            uint32_t* dW = sW + st * W_ST_W;
            const uint32_t* srcW = Wg + (size_t)kt * KTW * ldw;
#pragma unroll
            for (int i = 0; i < 4; i++) {
                int c = tid + i * 128;
                int row = c >> 5, ch = c & 31;  // 16 rows x 32 chunks
                cpasync16(dW + row * BSTR + ch * 4, srcW + (size_t)row * ldw + ch * 4);
            }
            asm volatile("cp.async.commit_group;\n");
        };

        load_tiles(0, 0);
        if (KT > 1) load_tiles(1, 1);

        for (int kt = 0; kt < KT; ++kt) {
            if (kt == KT - 1) {
                asm volatile("cp.async.wait_group 0;\n");
            } else {
                asm volatile("cp.async.wait_group 1;\n");
            }
            __syncthreads();
            const uint32_t aBase = sA_sh + (uint32_t)((kt & 1) * A_ST_W * 4) + a_lane_off;
            const uint32_t* w_ = sW + (kt & 1) * W_ST_W;
#pragma unroll
            for (int ks = 0; ks < 2; ++ks) {
                uint32_t af[2][4];
#pragma unroll
                for (int mi = 0; mi < 2; ++mi) {
                    uint32_t addr = aBase + (uint32_t)((mi * 16 * ASTR + ks * 8) * 4);
                    asm volatile(
                        "ldmatrix.sync.aligned.m8n8.x4.shared.b16 {%0,%1,%2,%3}, [%4];"
                        : "=r"(af[mi][0]), "=r"(af[mi][1]), "=r"(af[mi][2]), "=r"(af[mi][3])
                        : "r"(addr));
                }
                const int brow = (ks * 8 + tig) * BSTR + bcol;
#pragma unroll
                for (int ni = 0; ni < 4; ++ni) {
                    uint32_t b0 = w_[brow + ni * 8];
                    uint32_t b1 = w_[brow + 4 * BSTR + ni * 8];
#pragma unroll
                    for (int mi = 0; mi < 2; ++mi) {
                        asm volatile(
                            "mma.sync.aligned.m16n8k16.row.col.f32.bf16.bf16.f32 "
                            "{%0,%1,%2,%3},{%4,%5,%6,%7},{%8,%9},{%0,%1,%2,%3};\n"
                            : "+f"(acc[mi][ni][0]), "+f"(acc[mi][ni][1]),
                              "+f"(acc[mi][ni][2]), "+f"(acc[mi][ni][3])
                            : "r"(af[mi][0]), "r"(af[mi][1]), "r"(af[mi][2]), "r"(af[mi][3]),
                              "r"(b0), "r"(b1));
                    }
                }
            }
            __syncthreads();
            if (kt + 2 < KT) load_tiles(kt + 2, kt & 1);
        }

        float* C = (FLAGS == F_RAW) ? (split ? C1 : C0) : nullptr;
#pragma unroll
        for (int mi = 0; mi < 2; mi++) {
            int row0 = group * GROWS + mi * 16 + gid;
#pragma unroll
            for (int ni = 0; ni < 4; ni++) {
                int col = bn * 128 + warp * 32 + ni * 8 + tig * 2;
                if (FLAGS == F_EPI) {
                    float2 bv = *(const float2*)(bias + col);
                    float x0 = fmaxf(acc[mi][ni][0] + bv.x, 0.f);
                    float y0 = fmaxf(acc[mi][ni][1] + bv.y, 0.f);
                    float x1 = fmaxf(acc[mi][ni][2] + bv.x, 0.f);
                    float y1 = fmaxf(acc[mi][ni][3] + bv.y, 0.f);
                    C0p[(size_t)row0 * (N / 2) + (col >> 1)] = pkbf(x0, y0);
                    C0p[(size_t)(row0 + 8) * (N / 2) + (col >> 1)] = pkbf(x1, y1);
                } else {
                    float2 v0, v1;
                    v0.x = acc[mi][ni][0];
                    v0.y = acc[mi][ni][1];
                    v1.x = acc[mi][ni][2];
                    v1.y = acc[mi][ni][3];
                    *(float2*)(C + (size_t)row0 * N + col) = v0;
                    *(float2*)(C + (size_t)(row0 + 8) * N + col) = v1;
                }
            }
        }
    }
}

// ---------------------------------------------------------------------------
// Persistent kernel: 1024 CTAs (7/SM, 28 warps/SM), 8-CTA groups own 32 rows.
// ---------------------------------------------------------------------------
__global__ __launch_bounds__(GTHR, 7) void persistent_kernel(
    const int* __restrict__ a_seq, const int* __restrict__ b_seq,
    const float* __restrict__ bit_emb, const float* __restrict__ start_state,
    const float* __restrict__ ln1_g, const float* __restrict__ ln1_b,
    const float* __restrict__ qkv_w, const float* __restrict__ qkv_b,
    const float* __restrict__ out_w, const float* __restrict__ out_b,
    const float* __restrict__ ln2_g, const float* __restrict__ ln2_b,
    const float* __restrict__ ff1_w, const float* __restrict__ ff1_b,
    const float* __restrict__ ff2_w, const float* __restrict__ ff2_b,
    const float* __restrict__ head_w, const float* __restrict__ head_b, float* __restrict__ out) {
    extern __shared__ uint32_t sm[];

    const int group = blockIdx.x >> 3;
    const int rank = blockIdx.x & 7;

    prep_phase(qkv_w, qkv_b, out_w, out_b, ff1_w, ff2_w);
    emb0_phase(a_seq, b_seq, bit_emb, start_state);
    grid_bar();

    for (int t = 0; t < NS; ++t) {
        for (int l = 0; l < NDEPTH; ++l) {
            // LN1: plain at l==0; else fuse ff2 reduce of l-1
            if (l == 0)
                ln_phase<false>(group, rank, g_x, g_yp, nullptr, nullptr, nullptr,
                                ln1_g + l * ND, ln1_b + l * ND);
            else
                ln_phase<true>(group, rank, g_x, g_yp, g_p0, g_p1,
                               ff2_b + (size_t)(l - 1) * ND, ln1_g + l * ND, ln1_b + l * ND);
            group_bar(group);
            // Wc GEMM (split-K 2, KT=8 each): p0/p1 = y @ Wc  (BN=128, 8 jobs)
            gemm_phase<F_RAW>(group, rank, g_yp, ND / 2, g_wcp + (size_t)l * (ND / 2) * ND, ND,
                              nullptr, g_p0, g_p1, nullptr, ND, 8, 2, sm);
            group_bar(group);
            // LN2 fused: x += p0+p1+bc; y = LN2(x) packed
            ln_phase<true>(group, rank, g_x, g_yp, g_p0, g_p1, g_bc + l * ND, ln2_g + l * ND,
                           ln2_b + l * ND);
            group_bar(group);
            // h = pack(relu(y @ W1 + b1))  (BN=128, 16 jobs, KT=16)
            gemm_phase<F_EPI>(group, rank, g_yp, ND / 2, g_w1p + (size_t)l * (ND / 2) * 4 * ND,
                              4 * ND, ff1_b + (size_t)l * 4 * ND, nullptr, nullptr, g_hp,
                              4 * ND, 16, 1, sm);
            group_bar(group);
            // ff2 (split-K 2, KT=32): p0/p1 = h @ W2  (BN=128, 8 jobs)
            gemm_phase<F_RAW>(group, rank, g_hp, 2 * ND, g_w2p + (size_t)l * 2 * ND * ND, ND,
                              nullptr, g_p0, g_p1, nullptr, ND, 32, 2, sm);
            group_bar(group);
        }
        heademb_phase(group, rank, g_p0, g_p1, ff2_b + (size_t)(NDEPTH - 1) * ND, head_w,
                      head_b, out, a_seq, b_seq, bit_emb, t);
        group_bar(group);
    }
}

// ---------------------------------------------------------------------------
extern "C" void kernel_launch(void* const* d_in, const int* in_sizes, int n_in,
                              void* d_out, int out_size) {
    const int* a_seq = (const int*)d_in[0];
    const int* b_seq = (const int*)d_in[1];
    const float* bit_emb = (const float*)d_in[2];
    const float* start_state = (const float*)d_in[3];
    const float* ln1_g = (const float*)d_in[4];
    const float* ln1_b = (const float*)d_in[5];
    const float* qkv_w = (const float*)d_in[6];
    const float* qkv_b = (const float*)d_in[7];
    const float* out_w = (const float*)d_in[8];
    const float* out_b = (const float*)d_in[9];
    const float* ln2_g = (const float*)d_in[10];
    const float* ln2_b = (const float*)d_in[11];
    const float* ff1_w = (const float*)d_in[12];
    const float* ff1_b = (const float*)d_in[13];
    const float* ff2_w = (const float*)d_in[14];
    const float* ff2_b = (const float*)d_in[15];
    const float* head_w = (const float*)d_in[16];
    const float* head_b = (const float*)d_in[17];
    float* out = (float*)d_out;

    const int smem = SMEM_W * (int)sizeof(uint32_t);
    static int configured = 0;
    if (!configured) {
        cudaFuncSetAttribute(persistent_kernel, cudaFuncAttributeMaxDynamicSharedMemorySize, smem);
        configured = 1;
    }

    persistent_kernel<<<GBLK, GTHR, smem>>>(a_seq, b_seq, bit_emb, start_state, ln1_g, ln1_b,
                                            qkv_w, qkv_b, out_w, out_b, ln2_g, ln2_b, ff1_w,
                                            ff1_b, ff2_w, ff2_b, head_w, head_b, out);
}

// round 17
// speedup vs baseline: 1.1463x; 1.0410x over previous
#include <cuda_runtime.h>
#include <cstdint>

#define NB 4096
#define NS 64
#define ND 512
#define NDEPTH 4
#define LN_EPS 1e-5f

#define KTW 32     // packed words per ktile (= 64 k-values)
#define ASTR 36    // A smem row stride in words (32 data + 4 pad)

#define GBLK 512
#define GTHR 128
#define NGRP 64      // 64 groups x 8 CTAs; group owns 64 rows
#define GRP_BLKS 8
#define GROWS 64     // rows per group

#define A_ST_W (GROWS * ASTR)             // 2304 words per A stage
#define W_ST_W (16 * 132 * 2)             // 4224 words per B stage (16 uint2-rows, NI=8)
#define SMEM_W (2 * A_ST_W + 2 * W_ST_W)  // 13056 words = 52224 B

#define F_RAW 0
#define F_EPI 1  // bias + relu + pack-to-bf16 (ff1 -> h)
#define F_RES 2  // x += acc + bias (Wc residual RMW)

// Activation scratch
static __device__ __align__(128) float g_x[NB * ND];           // residual (fp32)
static __device__ __align__(128) uint32_t g_yp[NB * ND / 2];   // LN out, bf16x2 packed
static __device__ __align__(128) uint32_t g_hp[NB * 2 * ND];   // ff1 out, bf16x2 packed
static __device__ __align__(128) float g_p0[NB * ND];          // ff2 split-K partial 0
static __device__ __align__(128) float g_p1[NB * ND];          // ff2 split-K partial 1
// Paired packed weights: uint2 row Q pairs word-rows kk0=(Q>>4)*32+((Q>>2)&3)*8+(Q&3)
// [.x] and kk0+4 [.y]; each word = (bf16 W[2kk][n], bf16 W[2kk+1][n]).
static __device__ __align__(128) uint32_t g_wcp[NDEPTH * (ND / 2) * ND];
static __device__ __align__(128) uint32_t g_w1p[NDEPTH * (ND / 2) * 4 * ND];
static __device__ __align__(128) uint32_t g_w2p[NDEPTH * 2 * ND * ND];
static __device__ float g_bc[NDEPTH * ND];  // bv @ Wo + bo (fp32)

// Global barrier (used once) + per-group barriers (own cachelines)
static __device__ unsigned g_bar = 0;
static __device__ volatile unsigned g_epoch = 0;
static __device__ __align__(128) unsigned g_gcnt[NGRP * 32];
static __device__ __align__(128) volatile unsigned g_gep[NGRP * 32];

__device__ __forceinline__ void grid_bar() {
    __threadfence();
    __syncthreads();
    if (threadIdx.x == 0) {
        unsigned e = g_epoch;
        if (atomicAdd(&g_bar, 1u) == GBLK - 1) {
            g_bar = 0;
            __threadfence();
            g_epoch = e + 1;
        } else {
            while (g_epoch == e) __nanosleep(32);
            __threadfence();
        }
    }
    __syncthreads();
}

__device__ __forceinline__ void group_bar(int g) {
    __threadfence();
    __syncthreads();
    if (threadIdx.x == 0) {
        unsigned e = g_gep[g * 32];
        if (atomicAdd(&g_gcnt[g * 32], 1u) == GRP_BLKS - 1) {
            g_gcnt[g * 32] = 0;
            __threadfence();
            g_gep[g * 32] = e + 1;
        } else {
            while (g_gep[g * 32] == e) __nanosleep(20);
            __threadfence();
        }
    }
    __syncthreads();
}

__device__ __forceinline__ float warp_sum(float v) {
#pragma unroll
    for (int o = 16; o > 0; o >>= 1) v += __shfl_xor_sync(0xffffffffu, v, o);
    return v;
}

__device__ __forceinline__ uint32_t pkbf(float lo, float hi) {
    uint32_t r;
    asm("cvt.rn.bf16x2.f32 %0, %1, %2;" : "=r"(r) : "f"(hi), "f"(lo));
    return r;
}

__device__ __forceinline__ void cpasync16(void* smem, const void* gmem) {
    uint32_t sa = (uint32_t)__cvta_generic_to_shared(smem);
    asm volatile("cp.async.cg.shared.global [%0], [%1], 16;\n" ::"r"(sa), "l"(gmem));
}

// ---------------------------------------------------------------------------
// One-time prep: Wc = Wv @ Wo; bc; ff1/ff2. Paired uint2-row layout.
// Iterates over uint2 elements j; writes words 2j (x) and 2j+1 (y).
// ---------------------------------------------------------------------------
__device__ void prep_phase(const float* __restrict__ qkv_w, const float* __restrict__ qkv_b,
                           const float* __restrict__ out_w, const float* __restrict__ out_b,
                           const float* __restrict__ ff1_w, const float* __restrict__ ff2_w) {
    const int gtid = blockIdx.x * GTHR + threadIdx.x;
    const int stride = GBLK * GTHR;
    // Wc: 128 uint2-rows x 512 cols per layer (j-layer span 2^16)
    for (int j = gtid; j < NDEPTH * 128 * ND; j += stride) {
        int n = j & (ND - 1), Q = (j >> 9) & 127, l = j >> 16;
        int kk0 = ((Q >> 4) << 5) + (((Q >> 2) & 3) << 3) + (Q & 3);
#pragma unroll
        for (int slot = 0; slot < 2; slot++) {
            int kk = kk0 + slot * 4;
            const float* wv0 = qkv_w + ((size_t)l * ND + 2 * kk) * (3 * ND) + 2 * ND;
            const float* wv1 = wv0 + 3 * ND;
            const float* wo = out_w + (size_t)l * ND * ND + n;
            float s0 = 0.f, s1 = 0.f;
#pragma unroll 4
            for (int q = 0; q < ND; q++) {
                float w = wo[(size_t)q * ND];
                s0 += wv0[q] * w;
                s1 += wv1[q] * w;
            }
            g_wcp[2 * (size_t)j + slot] = pkbf(s0, s1);
        }
    }
    for (int i = gtid; i < NDEPTH * ND; i += stride) {
        int n = i & (ND - 1), l = i >> 9;
        const float* bv = qkv_b + l * 3 * ND + 2 * ND;
        const float* wo = out_w + (size_t)l * ND * ND + n;
        float s = out_b[l * ND + n];
#pragma unroll 4
        for (int q = 0; q < ND; q++) s += bv[q] * wo[(size_t)q * ND];
        g_bc[i] = s;
    }
    // ff1: 128 uint2-rows x 2048 cols per layer (span 2^18)
    for (int j = gtid; j < NDEPTH * 128 * 4 * ND; j += stride) {
        int n = j & (4 * ND - 1), Q = (j >> 11) & 127, l = j >> 18;
        int kk0 = ((Q >> 4) << 5) + (((Q >> 2) & 3) << 3) + (Q & 3);
#pragma unroll
        for (int slot = 0; slot < 2; slot++) {
            int kk = kk0 + slot * 4;
            size_t base = ((size_t)l * ND + 2 * kk) * (4 * ND) + n;
            g_w1p[2 * (size_t)j + slot] = pkbf(ff1_w[base], ff1_w[base + 4 * ND]);
        }
    }
    // ff2: 512 uint2-rows x 512 cols per layer (span 2^18)
    for (int j = gtid; j < NDEPTH * 512 * ND; j += stride) {
        int n = j & (ND - 1), Q = (j >> 9) & 511, l = j >> 18;
        int kk0 = ((Q >> 4) << 5) + (((Q >> 2) & 3) << 3) + (Q & 3);
#pragma unroll
        for (int slot = 0; slot < 2; slot++) {
            int kk = kk0 + slot * 4;
            size_t base = ((size_t)l * 4 * ND + 2 * kk) * ND + n;
            g_w2p[2 * (size_t)j + slot] = pkbf(ff2_w[base], ff2_w[base + ND]);
        }
    }
}

// ---------------------------------------------------------------------------
// emb0: global-strided (before the single grid barrier)
// ---------------------------------------------------------------------------
__device__ void emb0_phase(const int* __restrict__ a_seq, const int* __restrict__ b_seq,
                           const float* __restrict__ emb, const float* __restrict__ start) {
    int gw = blockIdx.x * 4 + (threadIdx.x >> 5);
    int lane = threadIdx.x & 31;
    for (int row = gw; row < NB; row += GBLK * 4) {
        int a = a_seq[row * NS];
        int b = b_seq[row * NS];
        const float4* ea = (const float4*)(emb + (size_t)a * ND);
        const float4* eb = (const float4*)(emb + (size_t)b * ND);
        const float4* ss = (const float4*)start;
        float4* xr = (float4*)(g_x + (size_t)row * ND);
#pragma unroll
        for (int j = 0; j < 4; j++) {
            int c = lane + 32 * j;
            float4 va = ea[c], vb = eb[c], vs = ss[c];
            float4 o;
            o.x = va.x + vb.x + vs.x;
            o.y = va.y + vb.y + vs.y;
            o.z = va.z + vb.z + vs.z;
            o.w = va.w + vb.w + vs.w;
            xr[c] = o;
        }
    }
}

// ---------------------------------------------------------------------------
// Group-scoped LN: rows [group*64, group*64+64), 32 warps -> 2 rows each.
// ---------------------------------------------------------------------------
template <bool FUSE>
__device__ void ln_phase(int group, int rank, float* __restrict__ x,
                         uint32_t* __restrict__ yp, const float* __restrict__ p0,
                         const float* __restrict__ p1, const float* __restrict__ addb,
                         const float* __restrict__ g, const float* __restrict__ b) {
    int w = rank * 4 + (threadIdx.x >> 5);
    int lane = threadIdx.x & 31;
    for (int rr = w; rr < GROWS; rr += 32) {
        int row = group * GROWS + rr;
        float4* xr = (float4*)(x + (size_t)row * ND);
        float4 v[4];
        float s = 0.f;
#pragma unroll
        for (int j = 0; j < 4; j++) {
            int c = lane + 32 * j;
            v[j] = xr[c];
            if (FUSE) {
                float4 a0 = ((const float4*)(p0 + (size_t)row * ND))[c];
                float4 a1 = ((const float4*)(p1 + (size_t)row * ND))[c];
                float4 ab = ((const float4*)addb)[c];
                v[j].x += a0.x + a1.x + ab.x;
                v[j].y += a0.y + a1.y + ab.y;
                v[j].z += a0.z + a1.z + ab.z;
                v[j].w += a0.w + a1.w + ab.w;
                xr[c] = v[j];
            }
            s += v[j].x + v[j].y + v[j].z + v[j].w;
        }
        s = warp_sum(s);
        float mean = s * (1.0f / ND);
        float q = 0.f;
#pragma unroll
        for (int j = 0; j < 4; j++) {
            float cx = v[j].x - mean, cy = v[j].y - mean;
            float cz = v[j].z - mean, cw = v[j].w - mean;
            q += cx * cx + cy * cy + cz * cz + cw * cw;
        }
        q = warp_sum(q);
        float r = rsqrtf(q * (1.0f / ND) + LN_EPS);
        uint2* yr = (uint2*)(yp + (size_t)row * (ND / 2));
#pragma unroll
        for (int j = 0; j < 4; j++) {
            int c = lane + 32 * j;
            float4 gg = ((const float4*)g)[c];
            float4 bb = ((const float4*)b)[c];
            uint2 o;
            o.x = pkbf((v[j].x - mean) * r * gg.x + bb.x, (v[j].y - mean) * r * gg.y + bb.y);
            o.y = pkbf((v[j].z - mean) * r * gg.z + bb.z, (v[j].w - mean) * r * gg.w + bb.w);
            yr[c] = o;
        }
    }
}

// ---------------------------------------------------------------------------
// Group-scoped head with fused ff2 reduce: x += p0+p1+b2; logits; x += emb(t+1).
// ---------------------------------------------------------------------------
__device__ void heademb_phase(int group, int rank, const float* __restrict__ p0,
                              const float* __restrict__ p1, const float* __restrict__ addb,
                              const float* __restrict__ hw, const float* __restrict__ hb,
                              float* __restrict__ out, const int* __restrict__ a_seq,
                              const int* __restrict__ b_seq, const float* __restrict__ emb,
                              int t) {
    int w = rank * 4 + (threadIdx.x >> 5);
    int lane = threadIdx.x & 31;
    for (int rr = w; rr < GROWS; rr += 32) {
        int row = group * GROWS + rr;
        float4* xr = (float4*)(g_x + (size_t)row * ND);
        float4 v[4];
        float s0 = 0.f, s1 = 0.f;
#pragma unroll
        for (int j = 0; j < 4; j++) {
            int c = lane + 32 * j;
            v[j] = xr[c];
            float4 a0 = ((const float4*)(p0 + (size_t)row * ND))[c];
            float4 a1 = ((const float4*)(p1 + (size_t)row * ND))[c];
            float4 ab = ((const float4*)addb)[c];
            v[j].x += a0.x + a1.x + ab.x;
            v[j].y += a0.y + a1.y + ab.y;
            v[j].z += a0.z + a1.z + ab.z;
            v[j].w += a0.w + a1.w + ab.w;
#pragma unroll
            for (int u = 0; u < 4; u++) {
                float xv = (&v[j].x)[u];
                float2 wv = ((const float2*)hw)[c * 4 + u];
                s0 += xv * wv.x;
                s1 += xv * wv.y;
            }
        }
        s0 = warp_sum(s0);
        s1 = warp_sum(s1);
        if (lane == 0) {
            out[(size_t)row * NS * 2 + t * 2 + 0] = s0 + hb[0];
            out[(size_t)row * NS * 2 + t * 2 + 1] = s1 + hb[1];
        }
        if (t + 1 < NS) {
            int a = a_seq[row * NS + t + 1];
            int b = b_seq[row * NS + t + 1];
            const float4* ea = (const float4*)(emb + (size_t)a * ND);
            const float4* eb = (const float4*)(emb + (size_t)b * ND);
#pragma unroll
            for (int j = 0; j < 4; j++) {
                int c = lane + 32 * j;
                v[j].x += ea[c].x + eb[c].x;
                v[j].y += ea[c].y + eb[c].y;
                v[j].z += ea[c].z + eb[c].z;
                v[j].w += ea[c].w + eb[c].w;
                xr[c] = v[j];
            }
        } else {
#pragma unroll
            for (int j = 0; j < 4; j++) xr[lane + 32 * j] = v[j];
        }
    }
}

// ---------------------------------------------------------------------------
// BF16 GEMM: 4-warp CTA, block tile 64 x (NI*16), warp tile 32 x (NI*8),
// mma.m16n8k16 (fp32 acc), ktile = 64 k, 2-stage cp.async.
// A via ldmatrix.x4; B via paired uint2 rows (one LDS.64 per (ks,ni)).
// ---------------------------------------------------------------------------
template <int NI, int FLAGS>
__device__ void gemm_phase(int group, int rank, const uint32_t* __restrict__ Aw, int Kw,
                           const uint32_t* __restrict__ Wp, int Nfull,
                           const float* __restrict__ bias, float* __restrict__ Cx,
                           float* __restrict__ C0, float* __restrict__ C1,
                           uint32_t* __restrict__ C0p, int N, int KT, int nsplit,
                           uint32_t* sm) {
    const int BQ2 = NI * 16 + 4;  // uint2 stride per B smem row
    uint32_t* sA = sm;
    uint32_t* sW = sm + 2 * A_ST_W;

    const int tid = threadIdx.x;
    const int warp = tid >> 5, lane = tid & 31;
    const int wm = warp >> 1, wn = warp & 1;  // 2 x 2 warp grid
    const int gid = lane >> 2, tig = lane & 3;

    const int bcol2 = wn * NI * 8 + gid;  // uint2 col base

    const uint32_t a_lane_off =
        ((uint32_t)((wm * 32 + (lane & 7) + ((lane >> 3) & 1) * 8) * ASTR + (lane >> 4) * 4))
        << 2;
    const uint32_t sA_sh = (uint32_t)__cvta_generic_to_shared(sA);

    const int ldwW = 2 * Nfull;  // words per global uint2-row

    const int nT = N / (NI * 16);
    const int njobs = nT * nsplit;

    for (int job = rank; job < njobs; job += GRP_BLKS) {
        const int split = job / nT;
        const int bn = job % nT;
        const uint32_t* Ag = Aw + (size_t)(group * GROWS) * Kw + split * KT * KTW;
        // global: uint2-row base split*KT*16, col base bn*NI*16 uint2 = *2 words
        const uint32_t* Wg = Wp + (size_t)(split * KT * 16) * ldwW + bn * NI * 16 * 2;

        float acc[2][NI][4];
#pragma unroll
        for (int i = 0; i < 2; i++)
#pragma unroll
            for (int j = 0; j < NI; j++)
#pragma unroll
                for (int k = 0; k < 4; k++) acc[i][j][k] = 0.f;

        auto load_tiles = [&](int kt, int st) {
            uint32_t* dA = sA + st * A_ST_W;
            const uint32_t* srcA = Ag + kt * KTW;
#pragma unroll
            for (int i = 0; i < 4; i++) {
                int c = tid + i * 128;
                int row = c >> 3, ch = c & 7;
                cpasync16(dA + row * ASTR + ch * 4, srcA + (size_t)row * Kw + ch * 4);
            }
            uint32_t* dW = sW + st * W_ST_W;
            const uint32_t* srcW = Wg + (size_t)kt * 16 * ldwW;
#pragma unroll
            for (int i = 0; i < NI; i++) {
                int c = tid + i * 128;
                int row = c / (NI * 8), ch = c % (NI * 8);  // 16 rows x NI*8 16B-chunks
                cpasync16(dW + row * (BQ2 * 2) + ch * 4, srcW + (size_t)row * ldwW + ch * 4);
            }
            asm volatile("cp.async.commit_group;\n");
        };

        load_tiles(0, 0);
        if (KT > 1) load_tiles(1, 1);

        for (int kt = 0; kt < KT; ++kt) {
            if (kt == KT - 1) {
                asm volatile("cp.async.wait_group 0;\n");
            } else {
                asm volatile("cp.async.wait_group 1;\n");
            }
            __syncthreads();
            const uint32_t aBase = sA_sh + (uint32_t)((kt & 1) * A_ST_W * 4) + a_lane_off;
            const uint2* w2_ = (const uint2*)(sW + (kt & 1) * W_ST_W);
#pragma unroll
            for (int ks = 0; ks < 4; ++ks) {
                uint32_t af[2][4];
#pragma unroll
                for (int mi = 0; mi < 2; ++mi) {
                    uint32_t addr = aBase + (uint32_t)((mi * 16 * ASTR + ks * 8) * 4);
                    asm volatile(
                        "ldmatrix.sync.aligned.m8n8.x4.shared.b16 {%0,%1,%2,%3}, [%4];"
                        : "=r"(af[mi][0]), "=r"(af[mi][1]), "=r"(af[mi][2]), "=r"(af[mi][3])
                        : "r"(addr));
                }
                const int qrow = (ks * 4 + tig) * BQ2 + bcol2;
#pragma unroll
                for (int ni = 0; ni < NI; ++ni) {
                    uint2 qb = w2_[qrow + ni * 8];  // b0 (.x), b1 (.y) paired
#pragma unroll
                    for (int mi = 0; mi < 2; ++mi) {
                        asm volatile(
                            "mma.sync.aligned.m16n8k16.row.col.f32.bf16.bf16.f32 "
                            "{%0,%1,%2,%3},{%4,%5,%6,%7},{%8,%9},{%0,%1,%2,%3};\n"
                            : "+f"(acc[mi][ni][0]), "+f"(acc[mi][ni][1]),
                              "+f"(acc[mi][ni][2]), "+f"(acc[mi][ni][3])
                            : "r"(af[mi][0]), "r"(af[mi][1]), "r"(af[mi][2]), "r"(af[mi][3]),
                              "r"(qb.x), "r"(qb.y));
                    }
                }
            }
            __syncthreads();
            if (kt + 2 < KT) load_tiles(kt + 2, kt & 1);
        }

        float* C = (FLAGS == F_RAW) ? (split ? C1 : C0) : nullptr;
#pragma unroll
        for (int mi = 0; mi < 2; mi++) {
            int row0 = group * GROWS + wm * 32 + mi * 16 + gid;
#pragma unroll
            for (int ni = 0; ni < NI; ni++) {
                int col = bn * NI * 16 + wn * NI * 8 + ni * 8 + tig * 2;
                if (FLAGS == F_RES) {
                    float2 bv = *(const float2*)(bias + col);
                    float2* px0 = (float2*)(Cx + (size_t)row0 * N + col);
                    float2* px1 = (float2*)(Cx + (size_t)(row0 + 8) * N + col);
                    float2 x0 = *px0, x1 = *px1;
                    x0.x += acc[mi][ni][0] + bv.x;
                    x0.y += acc[mi][ni][1] + bv.y;
                    x1.x += acc[mi][ni][2] + bv.x;
                    x1.y += acc[mi][ni][3] + bv.y;
                    *px0 = x0;
                    *px1 = x1;
                } else if (FLAGS == F_EPI) {
                    float2 bv = *(const float2*)(bias + col);
                    float x0 = fmaxf(acc[mi][ni][0] + bv.x, 0.f);
                    float y0 = fmaxf(acc[mi][ni][1] + bv.y, 0.f);
                    float x1 = fmaxf(acc[mi][ni][2] + bv.x, 0.f);
                    float y1 = fmaxf(acc[mi][ni][3] + bv.y, 0.f);
                    C0p[(size_t)row0 * (N / 2) + (col >> 1)] = pkbf(x0, y0);
                    C0p[(size_t)(row0 + 8) * (N / 2) + (col >> 1)] = pkbf(x1, y1);
                } else {
                    float2 v0, v1;
                    v0.x = acc[mi][ni][0];
                    v0.y = acc[mi][ni][1];
                    v1.x = acc[mi][ni][2];
                    v1.y = acc[mi][ni][3];
                    *(float2*)(C + (size_t)row0 * N + col) = v0;
                    *(float2*)(C + (size_t)(row0 + 8) * N + col) = v1;
                }
            }
        }
    }
}

// ---------------------------------------------------------------------------
// Persistent kernel: 4 CTAs/SM, 8-CTA groups own 64 rows, group barriers only.
// ---------------------------------------------------------------------------
__global__ __launch_bounds__(GTHR, 4) void persistent_kernel(
    const int* __restrict__ a_seq, const int* __restrict__ b_seq,
    const float* __restrict__ bit_emb, const float* __restrict__ start_state,
    const float* __restrict__ ln1_g, const float* __restrict__ ln1_b,
    const float* __restrict__ qkv_w, const float* __restrict__ qkv_b,
    const float* __restrict__ out_w, const float* __restrict__ out_b,
    const float* __restrict__ ln2_g, const float* __restrict__ ln2_b,
    const float* __restrict__ ff1_w, const float* __restrict__ ff1_b,
    const float* __restrict__ ff2_w, const float* __restrict__ ff2_b,
    const float* __restrict__ head_w, const float* __restrict__ head_b, float* __restrict__ out) {
    extern __shared__ uint32_t sm[];

    const int group = blockIdx.x >> 3;
    const int rank = blockIdx.x & 7;

    prep_phase(qkv_w, qkv_b, out_w, out_b, ff1_w, ff2_w);
    emb0_phase(a_seq, b_seq, bit_emb, start_state);
    grid_bar();

    for (int t = 0; t < NS; ++t) {
        for (int l = 0; l < NDEPTH; ++l) {
            if (l == 0)
                ln_phase<false>(group, rank, g_x, g_yp, nullptr, nullptr, nullptr,
                                ln1_g + l * ND, ln1_b + l * ND);
            else
                ln_phase<true>(group, rank, g_x, g_yp, g_p0, g_p1,
                               ff2_b + (size_t)(l - 1) * ND, ln1_g + l * ND, ln1_b + l * ND);
            group_bar(group);
            // Wc GEMM: x += y @ Wc + bc  (BN=64, KT=8, 1 job/CTA, residual RMW)
            gemm_phase<4, F_RES>(group, rank, g_yp, ND / 2,
                                 g_wcp + (size_t)l * (ND / 2) * ND, ND, g_bc + l * ND, g_x,
                                 nullptr, nullptr, nullptr, ND, 8, 1, sm);
            group_bar(group);
            // LN2 plain
            ln_phase<false>(group, rank, g_x, g_yp, nullptr, nullptr, nullptr, ln2_g + l * ND,
                            ln2_b + l * ND);
            group_bar(group);
            // h = pack(relu(y @ W1 + b1))  (BN=128, KT=8, 2 jobs/CTA)
            gemm_phase<8, F_EPI>(group, rank, g_yp, ND / 2,
                                 g_w1p + (size_t)l * (ND / 2) * 4 * ND, 4 * ND,
                                 ff1_b + (size_t)l * 4 * ND, nullptr, nullptr, nullptr, g_hp,
                                 4 * ND, 8, 1, sm);
            group_bar(group);
            // ff2 (split-K 2, KT=16): p0/p1 = h @ W2  (BN=128, 1 job/CTA)
            gemm_phase<8, F_RAW>(group, rank, g_hp, 2 * ND, g_w2p + (size_t)l * 2 * ND * ND,
                                 ND, nullptr, nullptr, g_p0, g_p1, nullptr, ND, 16, 2, sm);
            group_bar(group);
        }
        heademb_phase(group, rank, g_p0, g_p1, ff2_b + (size_t)(NDEPTH - 1) * ND, head_w,
                      head_b, out, a_seq, b_seq, bit_emb, t);
        group_bar(group);
    }
}

// ---------------------------------------------------------------------------
extern "C" void kernel_launch(void* const* d_in, const int* in_sizes, int n_in,
                              void* d_out, int out_size) {
    const int* a_seq = (const int*)d_in[0];
    const int* b_seq = (const int*)d_in[1];
    const float* bit_emb = (const float*)d_in[2];
    const float* start_state = (const float*)d_in[3];
    const float* ln1_g = (const float*)d_in[4];
    const float* ln1_b = (const float*)d_in[5];
    const float* qkv_w = (const float*)d_in[6];
    const float* qkv_b = (const float*)d_in[7];
    const float* out_w = (const float*)d_in[8];
    const float* out_b = (const float*)d_in[9];
    const float* ln2_g = (const float*)d_in[10];
    const float* ln2_b = (const float*)d_in[11];
    const float* ff1_w = (const float*)d_in[12];
    const float* ff1_b = (const float*)d_in[13];
    const float* ff2_w = (const float*)d_in[14];
    const float* ff2_b = (const float*)d_in[15];
    const float* head_w = (const float*)d_in[16];
    const float* head_b = (const float*)d_in[17];
    float* out = (float*)d_out;

    const int smem = SMEM_W * (int)sizeof(uint32_t);
    static int configured = 0;
    if (!configured) {
        cudaFuncSetAttribute(persistent_kernel, cudaFuncAttributeMaxDynamicSharedMemorySize, smem);
        configured = 1;
    }

    persistent_kernel<<<GBLK, GTHR, smem>>>(a_seq, b_seq, bit_emb, start_state, ln1_g, ln1_b,
                                            qkv_w, qkv_b, out_w, out_b, ln2_g, ln2_b, ff1_w,
                                            ff1_b, ff2_w, ff2_b, head_w, head_b, out);
}